// round 2
// baseline (speedup 1.0000x reference)
#include <cuda_runtime.h>

// ---------------------------------------------------------------------------
// SSMDecoder: ys = 2*Re( scan(exp(L*dt), x@B_bar^T) @ C^T ) + D*x
// Shapes: Bsz=8, L=4096, H=512, P=256 (complex state stored as re/im planes).
// Pipeline:
//   k_setup      : lambda_bar, f=(lam_bar-1)/Lam, power table lam^k (k<=64)
//   k_fill       : G1 [512][512] (rows: re then im of f*B~), G2 [512][512]
//   k_gemm1      : Bu = x @ G1^T            (fp32, fma.rn.f32x2 micro-kernel)
//   k_scan_local : in-chunk inclusive scan (chunk=64), chunk sums
//   k_chunkscan  : scan of chunk sums with multiplier lam^64 -> carries
//   k_apply      : xs[l] = lam^{j+1} * carry + local[l]   (in place)
//   k_gemm2      : ys = xs @ G2^T + D*x
// ---------------------------------------------------------------------------

#define BSZ 8
#define LEN 4096
#define HH  512
#define PP  256
#define N2  512                 // 2*P (re plane then im plane)
#define MT  (BSZ*LEN)           // 32768
#define CHUNK 64
#define NCHUNK (LEN/CHUNK)      // 64

typedef unsigned long long u64;

// ------------------------------- scratch -----------------------------------
__device__ float g_Bu[(size_t)MT * N2];       // 64 MB: Bu then xs (in place)
__device__ float g_G1[N2 * HH];
__device__ float g_G2[HH * N2];
__device__ float g_lam[2 * PP];
__device__ float g_f[2 * PP];
__device__ float g_pow[(CHUNK + 1) * N2];     // pow[k][p] re @ +p, im @ +256+p
__device__ float g_cs[BSZ * NCHUNK * N2];
__device__ float g_carry[BSZ * NCHUNK * N2];

// ------------------------- f32x2 packed helpers ----------------------------
__device__ __forceinline__ u64 dup2(float a) {
    unsigned u = __float_as_uint(a);
    u64 r;
    asm("mov.b64 %0, {%1, %1};" : "=l"(r) : "r"(u));
    return r;
}
__device__ __forceinline__ void fma2(u64 &d, u64 a, u64 b) {
    asm("fma.rn.f32x2 %0, %1, %2, %0;" : "+l"(d) : "l"(a), "l"(b));
}
__device__ __forceinline__ float2 asf2(u64 v) {
    unsigned lo, hi;
    asm("mov.b64 {%0, %1}, %2;" : "=r"(lo), "=r"(hi) : "l"(v));
    float2 f;
    f.x = __uint_as_float(lo);
    f.y = __uint_as_float(hi);
    return f;
}

// ------------------------------- setup -------------------------------------
__global__ void k_setup(const float* __restrict__ lre,
                        const float* __restrict__ lim,
                        const float* __restrict__ lstep) {
    int p = threadIdx.x;
    if (p >= PP) return;
    float st = expf(lstep[p]);
    float ar = lre[p], ai = lim[p];
    float e  = expf(ar * st);
    float th = ai * st;
    float lr = e * cosf(th), li = e * sinf(th);
    g_lam[p] = lr; g_lam[PP + p] = li;
    // f = (lam_bar - 1) / Lam
    float nr = lr - 1.0f, ni = li;
    float den = ar * ar + ai * ai;
    g_f[p]      = (nr * ar + ni * ai) / den;
    g_f[PP + p] = (ni * ar - nr * ai) / den;
    // powers lam^k, k = 0..CHUNK
    float pr = 1.0f, pi = 0.0f;
    for (int k = 0; k <= CHUNK; k++) {
        g_pow[k * N2 + p]      = pr;
        g_pow[k * N2 + PP + p] = pi;
        float t = pr * lr - pi * li;
        pi = pr * li + pi * lr;
        pr = t;
    }
}

__global__ void k_fill(const float* __restrict__ Bm, const float* __restrict__ Cm) {
    int tid = blockIdx.x * blockDim.x + threadIdx.x;  // 0 .. 262143
    if (tid >= N2 * HH) return;
    {   // G1[n][h]
        int n = tid / HH, h = tid - n * HH;
        int p = n & (PP - 1);
        float fr = g_f[p], fi = g_f[PP + p];
        float b0 = Bm[(p * HH + h) * 2], b1 = Bm[(p * HH + h) * 2 + 1];
        g_G1[tid] = (n < PP) ? (fr * b0 - fi * b1) : (fr * b1 + fi * b0);
    }
    {   // G2[h][n]
        int h = tid / N2, n = tid - h * N2;
        float v;
        if (n < PP) v =  2.0f * Cm[(h * PP + n) * 2];
        else        v = -2.0f * Cm[(h * PP + (n - PP)) * 2 + 1];
        g_G2[tid] = v;
    }
}

// ------------------------------- GEMM --------------------------------------
// C[M x 512] = A[M x 512] @ B[512 x 512]^T  (both operands K-contiguous)
// Block tile 128x128, BK=8, 128 threads, micro-tile 16(M) x 8(N).
// Accumulators are f32x2 pairs along M (pairs come packed straight from SMEM).
#define BM 128
#define BN 128
#define BK 8
#define KT 512
#define NT 512

template <bool EPI>
__device__ __forceinline__ void gemm_body(const float* __restrict__ Ag,
                                          const float* __restrict__ Bg,
                                          float* __restrict__ Cg,
                                          const float* __restrict__ Xg,
                                          const float* __restrict__ Dg) {
    __shared__ __align__(16) float As[2][BK][BM + 4];
    __shared__ __align__(16) float Bs[2][BK][BN + 4];

    const int tid = threadIdx.x;
    const int tx = tid & 15;        // N direction, 8 cols each
    const int ty = tid >> 4;        // M direction, 16 rows each (0..7)
    const int rowBase = blockIdx.y * BM;
    const int colBase = blockIdx.x * BN;

    const int lrow = tid >> 1;          // 0..63
    const int lseg = (tid & 1) * 4;     // 0 or 4

    const float* aP = Ag + (size_t)(rowBase + lrow) * KT + lseg;
    const float* bP = Bg + (size_t)(colBase + lrow) * KT + lseg;

    float4 ra0 = *(const float4*)(aP);
    float4 ra1 = *(const float4*)(aP + (size_t)64 * KT);
    float4 rb0 = *(const float4*)(bP);
    float4 rb1 = *(const float4*)(bP + (size_t)64 * KT);

#pragma unroll
    for (int j = 0; j < 4; j++) {
        As[0][lseg + j][lrow]      = ((const float*)&ra0)[j];
        As[0][lseg + j][lrow + 64] = ((const float*)&ra1)[j];
        Bs[0][lseg + j][lrow]      = ((const float*)&rb0)[j];
        Bs[0][lseg + j][lrow + 64] = ((const float*)&rb1)[j];
    }
    __syncthreads();

    u64 acc[8][8];
#pragma unroll
    for (int i = 0; i < 8; i++)
#pragma unroll
        for (int j = 0; j < 8; j++) acc[i][j] = 0ull;

    int buf = 0;
    for (int kt = BK; kt <= KT; kt += BK) {
        const bool more = (kt < KT);
        if (more) {
            ra0 = *(const float4*)(aP + kt);
            ra1 = *(const float4*)(aP + (size_t)64 * KT + kt);
            rb0 = *(const float4*)(bP + kt);
            rb1 = *(const float4*)(bP + (size_t)64 * KT + kt);
        }
#pragma unroll
        for (int k = 0; k < BK; k++) {
            const float* ar = &As[buf][k][ty * 16];
            ulonglong2 q0 = *(const ulonglong2*)(ar);
            ulonglong2 q1 = *(const ulonglong2*)(ar + 4);
            ulonglong2 q2 = *(const ulonglong2*)(ar + 8);
            ulonglong2 q3 = *(const ulonglong2*)(ar + 12);
            u64 av[8] = {q0.x, q0.y, q1.x, q1.y, q2.x, q2.y, q3.x, q3.y};
            const float* br = &Bs[buf][k][tx * 8];
            float4 b0 = *(const float4*)(br);
            float4 b1 = *(const float4*)(br + 4);
            u64 bd[8] = {dup2(b0.x), dup2(b0.y), dup2(b0.z), dup2(b0.w),
                         dup2(b1.x), dup2(b1.y), dup2(b1.z), dup2(b1.w)};
#pragma unroll
            for (int mp = 0; mp < 8; mp++)
#pragma unroll
                for (int n = 0; n < 8; n++) fma2(acc[mp][n], av[mp], bd[n]);
        }
        if (more) {
            int nb = buf ^ 1;
#pragma unroll
            for (int j = 0; j < 4; j++) {
                As[nb][lseg + j][lrow]      = ((const float*)&ra0)[j];
                As[nb][lseg + j][lrow + 64] = ((const float*)&ra1)[j];
                Bs[nb][lseg + j][lrow]      = ((const float*)&rb0)[j];
                Bs[nb][lseg + j][lrow + 64] = ((const float*)&rb1)[j];
            }
        }
        __syncthreads();
        buf ^= 1;
    }

    // Epilogue: acc[mp][n] holds rows (2mp, 2mp+1) of this thread's 16 rows.
    const int col = colBase + tx * 8;
#pragma unroll
    for (int mp = 0; mp < 8; mp++) {
        const int r = rowBase + ty * 16 + 2 * mp;
        size_t off0 = (size_t)r * NT + col;
        float4 lo0, lo1, hi0, hi1;
        float2 c0 = asf2(acc[mp][0]), c1 = asf2(acc[mp][1]);
        float2 c2 = asf2(acc[mp][2]), c3 = asf2(acc[mp][3]);
        float2 c4 = asf2(acc[mp][4]), c5 = asf2(acc[mp][5]);
        float2 c6 = asf2(acc[mp][6]), c7 = asf2(acc[mp][7]);
        lo0 = make_float4(c0.x, c1.x, c2.x, c3.x);
        lo1 = make_float4(c4.x, c5.x, c6.x, c7.x);
        hi0 = make_float4(c0.y, c1.y, c2.y, c3.y);
        hi1 = make_float4(c4.y, c5.y, c6.y, c7.y);
        if (EPI) {
            float4 d0 = *(const float4*)(Dg + col);
            float4 d1 = *(const float4*)(Dg + col + 4);
            float4 x00 = *(const float4*)(Xg + off0);
            float4 x01 = *(const float4*)(Xg + off0 + 4);
            float4 x10 = *(const float4*)(Xg + off0 + NT);
            float4 x11 = *(const float4*)(Xg + off0 + NT + 4);
            lo0.x += d0.x * x00.x; lo0.y += d0.y * x00.y;
            lo0.z += d0.z * x00.z; lo0.w += d0.w * x00.w;
            lo1.x += d1.x * x01.x; lo1.y += d1.y * x01.y;
            lo1.z += d1.z * x01.z; lo1.w += d1.w * x01.w;
            hi0.x += d0.x * x10.x; hi0.y += d0.y * x10.y;
            hi0.z += d0.z * x10.z; hi0.w += d0.w * x10.w;
            hi1.x += d1.x * x11.x; hi1.y += d1.y * x11.y;
            hi1.z += d1.z * x11.z; hi1.w += d1.w * x11.w;
        }
        *(float4*)(Cg + off0)          = lo0;
        *(float4*)(Cg + off0 + 4)      = lo1;
        *(float4*)(Cg + off0 + NT)     = hi0;
        *(float4*)(Cg + off0 + NT + 4) = hi1;
    }
}

__global__ __launch_bounds__(128, 2) void k_gemm1(const float* __restrict__ x) {
    gemm_body<false>(x, g_G1, g_Bu, nullptr, nullptr);
}
__global__ __launch_bounds__(128, 2) void k_gemm2(const float* __restrict__ x,
                                                  const float* __restrict__ D,
                                                  float* __restrict__ out) {
    gemm_body<true>(g_Bu, g_G2, out, x, D);
}

// ------------------------------- scan --------------------------------------
__global__ void k_scan_local() {
    const int b = blockIdx.x >> 6;
    const int c = blockIdx.x & 63;
    const int p = threadIdx.x;  // 0..255
    const float lr = g_lam[p], li = g_lam[PP + p];
    float sr = 0.0f, si = 0.0f;
    size_t base = (size_t)(b * LEN + c * CHUNK) * N2;
#pragma unroll 4
    for (int j = 0; j < CHUNK; j++) {
        size_t o = base + (size_t)j * N2;
        float ur = g_Bu[o + p], ui = g_Bu[o + PP + p];
        float nr = fmaf(lr, sr, fmaf(-li, si, ur));
        float ni = fmaf(lr, si, fmaf(li, sr, ui));
        g_Bu[o + p] = nr;
        g_Bu[o + PP + p] = ni;
        sr = nr; si = ni;
    }
    int co = (b * NCHUNK + c) * N2;
    g_cs[co + p] = sr;
    g_cs[co + PP + p] = si;
}

__global__ void k_chunkscan() {
    const int b = blockIdx.x;
    const int p = threadIdx.x;
    const float tr = g_pow[CHUNK * N2 + p], ti = g_pow[CHUNK * N2 + PP + p];
    float sr = 0.0f, si = 0.0f;
#pragma unroll 4
    for (int c = 0; c < NCHUNK; c++) {
        int o = (b * NCHUNK + c) * N2;
        g_carry[o + p] = sr;
        g_carry[o + PP + p] = si;
        float cr = g_cs[o + p], ci = g_cs[o + PP + p];
        float nr = fmaf(tr, sr, fmaf(-ti, si, cr));
        float ni = fmaf(tr, si, fmaf(ti, sr, ci));
        sr = nr; si = ni;
    }
}

__global__ void k_apply() {
    const int b = blockIdx.x >> 6;
    const int c = blockIdx.x & 63;
    if (c == 0) return;  // carry is zero for the first chunk
    const int p = threadIdx.x;
    const int co = (b * NCHUNK + c) * N2;
    const float Sr = g_carry[co + p], Si = g_carry[co + PP + p];
    size_t base = (size_t)(b * LEN + c * CHUNK) * N2;
#pragma unroll 4
    for (int j = 0; j < CHUNK; j++) {
        float fr = g_pow[(j + 1) * N2 + p];
        float fi = g_pow[(j + 1) * N2 + PP + p];
        size_t o = base + (size_t)j * N2;
        float lv = g_Bu[o + p], iv = g_Bu[o + PP + p];
        g_Bu[o + p]      = fmaf(fr, Sr, fmaf(-fi, Si, lv));
        g_Bu[o + PP + p] = fmaf(fr, Si, fmaf(fi, Sr, iv));
    }
}

// ------------------------------ launcher -----------------------------------
extern "C" void kernel_launch(void* const* d_in, const int* in_sizes, int n_in,
                              void* d_out, int out_size) {
    (void)in_sizes; (void)n_in; (void)out_size;
    const float* x     = (const float*)d_in[0];
    const float* lre   = (const float*)d_in[1];
    const float* lim   = (const float*)d_in[2];
    const float* Bm    = (const float*)d_in[3];
    const float* Cm    = (const float*)d_in[4];
    const float* D     = (const float*)d_in[5];
    const float* lstep = (const float*)d_in[6];
    float* out = (float*)d_out;

    k_setup<<<1, 256>>>(lre, lim, lstep);
    k_fill<<<(N2 * HH + 255) / 256, 256>>>(Bm, Cm);

    dim3 gg(NT / BN, MT / BM);  // (4, 256)
    k_gemm1<<<gg, 128>>>(x);
    k_scan_local<<<BSZ * NCHUNK, 256>>>();
    k_chunkscan<<<BSZ, 256>>>();
    k_apply<<<BSZ * NCHUNK, 256>>>();
    k_gemm2<<<gg, 128>>>(x, D, out);
}

// round 6
// speedup vs baseline: 2.7103x; 2.7103x over previous
#include <cuda_runtime.h>
#include <cuda_bf16.h>
#include <cstdint>

// ---------------------------------------------------------------------------
// SSMDecoder: ys = 2*Re( scan(exp(L*dt), x@B_bar^T) @ C^T ) + D*x
// Bsz=8, L=4096, H=512, P=256 (complex state as re/im planes, N2=512).
// GEMMs via legacy mma.sync m16n8k16 bf16 with 3x hi/lo split (fp32-grade).
// (tcgen05 unavailable: harness PTX target is compute_103, not 103a.)
// ---------------------------------------------------------------------------

#define BSZ 8
#define LEN 4096
#define HH  512
#define PP  256
#define N2  512
#define MT  (BSZ*LEN)           // 32768
#define CHUNK 64
#define NCHUNK (LEN/CHUNK)      // 64
#define KT  512
#define NT  512

// ------------------------------- scratch -----------------------------------
__device__ float g_Bu[(size_t)MT * N2];       // 64 MB: Bu then xs (in place)
__device__ float g_G1[N2 * HH];
__device__ float g_G2[HH * N2];
__device__ float g_lam[2 * PP];
__device__ float g_f[2 * PP];
__device__ float g_pow[(CHUNK + 1) * N2];
__device__ float g_cs[BSZ * NCHUNK * N2];
__device__ float g_carry[BSZ * NCHUNK * N2];

// ------------------------------ helpers ------------------------------------
__device__ __forceinline__ uint32_t smem_u32(const void* p) {
    uint32_t a;
    asm("{ .reg .u64 t; cvta.to.shared.u64 t, %1; cvt.u32.u64 %0, t; }"
        : "=r"(a) : "l"(p));
    return a;
}

__device__ __forceinline__ void ldsm4(uint32_t* r, uint32_t addr) {
    asm volatile("ldmatrix.sync.aligned.m8n8.x4.shared.b16 {%0,%1,%2,%3}, [%4];"
                 : "=r"(r[0]), "=r"(r[1]), "=r"(r[2]), "=r"(r[3]) : "r"(addr));
}

__device__ __forceinline__ void mma_bf16(float* c, const uint32_t* a, const uint32_t* b) {
    asm volatile(
        "mma.sync.aligned.m16n8k16.row.col.f32.bf16.bf16.f32 "
        "{%0,%1,%2,%3}, {%4,%5,%6,%7}, {%8,%9}, {%0,%1,%2,%3};"
        : "+f"(c[0]), "+f"(c[1]), "+f"(c[2]), "+f"(c[3])
        : "r"(a[0]), "r"(a[1]), "r"(a[2]), "r"(a[3]), "r"(b[0]), "r"(b[1]));
}

__device__ __forceinline__ uint32_t packbf(float x, float y) {
    __nv_bfloat162 t = __floats2bfloat162_rn(x, y);
    return *reinterpret_cast<uint32_t*>(&t);
}

// ------------------------------- setup -------------------------------------
__global__ void k_setup(const float* __restrict__ lre,
                        const float* __restrict__ lim,
                        const float* __restrict__ lstep) {
    int p = threadIdx.x;
    if (p >= PP) return;
    float st = expf(lstep[p]);
    float ar = lre[p], ai = lim[p];
    float e  = expf(ar * st);
    float th = ai * st;
    float lr = e * cosf(th), li = e * sinf(th);
    g_lam[p] = lr; g_lam[PP + p] = li;
    float nr = lr - 1.0f, ni = li;
    float den = ar * ar + ai * ai;
    g_f[p]      = (nr * ar + ni * ai) / den;
    g_f[PP + p] = (ni * ar - nr * ai) / den;
    float pr = 1.0f, pi = 0.0f;
    for (int k = 0; k <= CHUNK; k++) {
        g_pow[k * N2 + p]      = pr;
        g_pow[k * N2 + PP + p] = pi;
        float t = pr * lr - pi * li;
        pi = pr * li + pi * lr;
        pr = t;
    }
}

__global__ void k_fill(const float* __restrict__ Bm, const float* __restrict__ Cm) {
    int tid = blockIdx.x * blockDim.x + threadIdx.x;
    if (tid >= N2 * HH) return;
    {   // G1[n][h]
        int n = tid / HH, h = tid - n * HH;
        int p = n & (PP - 1);
        float fr = g_f[p], fi = g_f[PP + p];
        float b0 = Bm[(p * HH + h) * 2], b1 = Bm[(p * HH + h) * 2 + 1];
        g_G1[tid] = (n < PP) ? (fr * b0 - fi * b1) : (fr * b1 + fi * b0);
    }
    {   // G2[h][n]
        int h = tid / N2, n = tid - h * N2;
        float v;
        if (n < PP) v =  2.0f * Cm[(h * PP + n) * 2];
        else        v = -2.0f * Cm[(h * PP + (n - PP)) * 2 + 1];
        g_G2[tid] = v;
    }
}

// --------------------------- mma.sync GEMM ---------------------------------
// C[M x 512] = A[M x 512] @ B[512 x 512]^T (both K-contiguous).
// CTA tile 128(M) x 128(N), K-chunk 32, 256 threads = 8 warps (2M x 4N),
// warp tile 64x32 => 4 m16-tiles x 4 n8-tiles = 16 mma per pass, 3 passes.
// SMEM: per stage 4 planes (Ah, Al, Bh, Bl), rows padded to 40 bf16 (80 B),
// which makes ldmatrix.x4's 8 row-addresses hit 8 distinct 16B banks.

#define AROW  40                        // bf16 elements per padded row
#define PLANE (128 * AROW * 2)          // 10240 B
#define STAGE (4 * PLANE)               // 40960 B
#define GSMEM (2 * STAGE)               // 81920 B

__device__ __forceinline__ void sts_stage(uint32_t base, int tid,
                                          const float4* ra, const float4* rb) {
#pragma unroll
    for (int i = 0; i < 4; i++) {
        int idx = tid + 256 * i;
        int r = idx >> 3, c4 = idx & 7;
        uint32_t off = (uint32_t)(r * (AROW * 2) + c4 * 8);
        // A hi/lo
        {
            float x0 = ra[i].x, x1 = ra[i].y, x2 = ra[i].z, x3 = ra[i].w;
            uint32_t h01 = packbf(x0, x1), h23 = packbf(x2, x3);
            float l0 = x0 - __bfloat162float(__float2bfloat16(x0));
            float l1 = x1 - __bfloat162float(__float2bfloat16(x1));
            float l2 = x2 - __bfloat162float(__float2bfloat16(x2));
            float l3 = x3 - __bfloat162float(__float2bfloat16(x3));
            uint32_t q01 = packbf(l0, l1), q23 = packbf(l2, l3);
            asm volatile("st.shared.v2.b32 [%0], {%1,%2};" ::
                         "r"(base + off), "r"(h01), "r"(h23) : "memory");
            asm volatile("st.shared.v2.b32 [%0], {%1,%2};" ::
                         "r"(base + PLANE + off), "r"(q01), "r"(q23) : "memory");
        }
        // B hi/lo
        {
            float x0 = rb[i].x, x1 = rb[i].y, x2 = rb[i].z, x3 = rb[i].w;
            uint32_t h01 = packbf(x0, x1), h23 = packbf(x2, x3);
            float l0 = x0 - __bfloat162float(__float2bfloat16(x0));
            float l1 = x1 - __bfloat162float(__float2bfloat16(x1));
            float l2 = x2 - __bfloat162float(__float2bfloat16(x2));
            float l3 = x3 - __bfloat162float(__float2bfloat16(x3));
            uint32_t q01 = packbf(l0, l1), q23 = packbf(l2, l3);
            asm volatile("st.shared.v2.b32 [%0], {%1,%2};" ::
                         "r"(base + 2 * PLANE + off), "r"(h01), "r"(h23) : "memory");
            asm volatile("st.shared.v2.b32 [%0], {%1,%2};" ::
                         "r"(base + 3 * PLANE + off), "r"(q01), "r"(q23) : "memory");
        }
    }
}

template <bool EPI>
__device__ __forceinline__ void gemm_mma(const float* __restrict__ Ag,
                                         const float* __restrict__ Bg,
                                         float* __restrict__ Cg,
                                         const float* __restrict__ Xg,
                                         const float* __restrict__ Dg) {
    extern __shared__ __align__(16) char smem[];
    const uint32_t sb = smem_u32(smem);
    const int tid = threadIdx.x;
    const int wid = tid >> 5;
    const int l   = tid & 31;
    const int warp_m = wid >> 2;        // 0..1  -> M offset *64
    const int warp_n = wid & 3;         // 0..3  -> N offset *32
    const int rowBase = blockIdx.y * 128;
    const int colBase = blockIdx.x * 128;

    float acc[4][4][4];
#pragma unroll
    for (int i = 0; i < 4; i++)
#pragma unroll
        for (int j = 0; j < 4; j++)
#pragma unroll
            for (int k = 0; k < 4; k++) acc[i][j][k] = 0.0f;

    const float* aG = Ag + (size_t)rowBase * KT;
    const float* bG = Bg + (size_t)colBase * KT;

    float4 ra[4], rb[4];
#pragma unroll
    for (int i = 0; i < 4; i++) {
        int idx = tid + 256 * i;
        int r = idx >> 3, c4 = idx & 7;
        ra[i] = *(const float4*)(aG + (size_t)r * KT + c4 * 4);
        rb[i] = *(const float4*)(bG + (size_t)r * KT + c4 * 4);
    }
    sts_stage(sb, tid, ra, rb);
    __syncthreads();

    // precomputed ldmatrix lane addressing
    const int a_row = l & 15;
    const int a_k   = (l >> 4) * 8;
    const int b_row = (l & 7) + ((l >> 4) << 3);
    const int b_k   = ((l >> 3) & 1) * 8;

    for (int kt = 0; kt < 16; kt++) {
        const int buf = kt & 1;
        if (kt < 15) {
#pragma unroll
            for (int i = 0; i < 4; i++) {
                int idx = tid + 256 * i;
                int r = idx >> 3, c4 = idx & 7;
                ra[i] = *(const float4*)(aG + (size_t)r * KT + (kt + 1) * 32 + c4 * 4);
                rb[i] = *(const float4*)(bG + (size_t)r * KT + (kt + 1) * 32 + c4 * 4);
            }
        }
        const uint32_t base = sb + buf * STAGE;
#pragma unroll
        for (int kk = 0; kk < 2; kk++) {
            uint32_t aH[4][4], aL[4][4], bH[2][4], bL[2][4];
            const int acol = kk * 16 + a_k;
            const int bcol = kk * 16 + b_k;
#pragma unroll
            for (int mt = 0; mt < 4; mt++) {
                uint32_t off = (uint32_t)(((warp_m * 64 + mt * 16 + a_row) * AROW + acol) * 2);
                ldsm4(aH[mt], base + off);
                ldsm4(aL[mt], base + PLANE + off);
            }
#pragma unroll
            for (int nb = 0; nb < 2; nb++) {
                uint32_t off = (uint32_t)(((warp_n * 32 + nb * 16 + b_row) * AROW + bcol) * 2);
                ldsm4(bH[nb], base + 2 * PLANE + off);
                ldsm4(bL[nb], base + 3 * PLANE + off);
            }
            // pass 1: Ah * Bh
#pragma unroll
            for (int mt = 0; mt < 4; mt++)
#pragma unroll
                for (int nt = 0; nt < 4; nt++)
                    mma_bf16(acc[mt][nt], aH[mt], &bH[nt >> 1][(nt & 1) * 2]);
            // pass 2: Al * Bh
#pragma unroll
            for (int mt = 0; mt < 4; mt++)
#pragma unroll
                for (int nt = 0; nt < 4; nt++)
                    mma_bf16(acc[mt][nt], aL[mt], &bH[nt >> 1][(nt & 1) * 2]);
            // pass 3: Ah * Bl
#pragma unroll
            for (int mt = 0; mt < 4; mt++)
#pragma unroll
                for (int nt = 0; nt < 4; nt++)
                    mma_bf16(acc[mt][nt], aH[mt], &bL[nt >> 1][(nt & 1) * 2]);
        }
        if (kt < 15) sts_stage(sb + (buf ^ 1) * STAGE, tid, ra, rb);
        __syncthreads();
    }

    // ---- epilogue ----
    const int r0 = l >> 2;
    const int cp = (l & 3) * 2;
#pragma unroll
    for (int mt = 0; mt < 4; mt++) {
#pragma unroll
        for (int nt = 0; nt < 4; nt++) {
            const int row = rowBase + warp_m * 64 + mt * 16 + r0;
            const int col = colBase + warp_n * 32 + nt * 8 + cp;
            float2 v0 = make_float2(acc[mt][nt][0], acc[mt][nt][1]);
            float2 v1 = make_float2(acc[mt][nt][2], acc[mt][nt][3]);
            size_t o0 = (size_t)row * NT + col;
            size_t o1 = (size_t)(row + 8) * NT + col;
            if (EPI) {
                float2 d  = *(const float2*)(Dg + col);
                float2 x0 = *(const float2*)(Xg + o0);
                float2 x1 = *(const float2*)(Xg + o1);
                v0.x += d.x * x0.x; v0.y += d.y * x0.y;
                v1.x += d.x * x1.x; v1.y += d.y * x1.y;
            }
            *(float2*)(Cg + o0) = v0;
            *(float2*)(Cg + o1) = v1;
        }
    }
}

__global__ __launch_bounds__(256, 1) void k_gemm1(const float* __restrict__ x) {
    gemm_mma<false>(x, g_G1, g_Bu, nullptr, nullptr);
}
__global__ __launch_bounds__(256, 1) void k_gemm2(const float* __restrict__ x,
                                                  const float* __restrict__ D,
                                                  float* __restrict__ out) {
    gemm_mma<true>(g_Bu, g_G2, out, x, D);
}

// ------------------------------- scan --------------------------------------
__global__ void k_scan_local() {
    const int b = blockIdx.x >> 6;
    const int c = blockIdx.x & 63;
    const int p = threadIdx.x;
    const float lr = g_lam[p], li = g_lam[PP + p];
    float sr = 0.0f, si = 0.0f;
    size_t base = (size_t)(b * LEN + c * CHUNK) * N2;
#pragma unroll 4
    for (int j = 0; j < CHUNK; j++) {
        size_t o = base + (size_t)j * N2;
        float ur = g_Bu[o + p], ui = g_Bu[o + PP + p];
        float nr = fmaf(lr, sr, fmaf(-li, si, ur));
        float ni = fmaf(lr, si, fmaf(li, sr, ui));
        g_Bu[o + p] = nr;
        g_Bu[o + PP + p] = ni;
        sr = nr; si = ni;
    }
    int co = (b * NCHUNK + c) * N2;
    g_cs[co + p] = sr;
    g_cs[co + PP + p] = si;
}

__global__ void k_chunkscan() {
    const int b = blockIdx.x;
    const int p = threadIdx.x;
    const float tr = g_pow[CHUNK * N2 + p], ti = g_pow[CHUNK * N2 + PP + p];
    float sr = 0.0f, si = 0.0f;
#pragma unroll 4
    for (int c = 0; c < NCHUNK; c++) {
        int o = (b * NCHUNK + c) * N2;
        g_carry[o + p] = sr;
        g_carry[o + PP + p] = si;
        float cr = g_cs[o + p], ci = g_cs[o + PP + p];
        float nr = fmaf(tr, sr, fmaf(-ti, si, cr));
        float ni = fmaf(tr, si, fmaf(ti, sr, ci));
        sr = nr; si = ni;
    }
}

__global__ void k_apply() {
    const int b = blockIdx.x >> 6;
    const int c = blockIdx.x & 63;
    if (c == 0) return;
    const int p = threadIdx.x;
    const int co = (b * NCHUNK + c) * N2;
    const float Sr = g_carry[co + p], Si = g_carry[co + PP + p];
    size_t base = (size_t)(b * LEN + c * CHUNK) * N2;
#pragma unroll 4
    for (int j = 0; j < CHUNK; j++) {
        float fr = g_pow[(j + 1) * N2 + p];
        float fi = g_pow[(j + 1) * N2 + PP + p];
        size_t o = base + (size_t)j * N2;
        float lv = g_Bu[o + p], iv = g_Bu[o + PP + p];
        g_Bu[o + p]      = fmaf(fr, Sr, fmaf(-fi, Si, lv));
        g_Bu[o + PP + p] = fmaf(fr, Si, fmaf(fi, Sr, iv));
    }
}

// ------------------------------ launcher -----------------------------------
extern "C" void kernel_launch(void* const* d_in, const int* in_sizes, int n_in,
                              void* d_out, int out_size) {
    (void)in_sizes; (void)n_in; (void)out_size;
    const float* x     = (const float*)d_in[0];
    const float* lre   = (const float*)d_in[1];
    const float* lim   = (const float*)d_in[2];
    const float* Bm    = (const float*)d_in[3];
    const float* Cm    = (const float*)d_in[4];
    const float* D     = (const float*)d_in[5];
    const float* lstep = (const float*)d_in[6];
    float* out = (float*)d_out;

    cudaFuncSetAttribute(k_gemm1, cudaFuncAttributeMaxDynamicSharedMemorySize, GSMEM);
    cudaFuncSetAttribute(k_gemm2, cudaFuncAttributeMaxDynamicSharedMemorySize, GSMEM);

    k_setup<<<1, 256>>>(lre, lim, lstep);
    k_fill<<<(N2 * HH + 255) / 256, 256>>>(Bm, Cm);

    dim3 gg(NT / 128, MT / 128);  // (4, 256)
    k_gemm1<<<gg, 256, GSMEM>>>(x);
    k_scan_local<<<BSZ * NCHUNK, 256>>>();
    k_chunkscan<<<BSZ, 256>>>();
    k_apply<<<BSZ * NCHUNK, 256>>>();
    k_gemm2<<<gg, 256, GSMEM>>>(x, D, out);
}